// round 10
// baseline (speedup 1.0000x reference)
#include <cuda_runtime.h>
#include <cuda_bf16.h>

#define NN 50000
#define NE 800000
#define DD 64
#define NG 1024
#define NL 4
#define BN_EPS 1e-5f

// ---------------- scratch (device globals) ----------------
__device__ __align__(16) float g_hw[NN * DD];         // (h @ W) * dinv[row]
__device__ __align__(16) float g_acc[NN * DD];        // pre-BN accumulator
__device__ __align__(16) float g_dinv[NN];
__device__ __align__(16) float g_stats[NL * 2 * DD];  // per-layer [sum, sumsq]
__device__ __align__(16) float g_pooled[NG * DD];
__device__ int g_rowptr[NN + 1];
__device__ int g_cursor[NN];
__device__ int g_csrc[NE];

__device__ __forceinline__ float4 f4add(float4 a, float4 b) {
    a.x += b.x; a.y += b.y; a.z += b.z; a.w += b.w; return a;
}

// ---------------- CSR build ----------------
__global__ void k_hist(const int* __restrict__ dst) {
    int e = blockIdx.x * blockDim.x + threadIdx.x;
    if (e < NE) atomicAdd(&g_cursor[dst[e]], 1);
}

__global__ __launch_bounds__(1024) void k_scan() {
    const int CH = (NN + 1023) / 1024;  // 49
    int tid = threadIdx.x;
    int base = tid * CH;
    int lim = min(base + CH, NN);
    int local = 0;
    for (int i = base; i < lim; i++) local += g_cursor[i];

    __shared__ int sh[1024];
    sh[tid] = local;
    __syncthreads();
    for (int off = 1; off < 1024; off <<= 1) {
        int v = (tid >= off) ? sh[tid - off] : 0;
        __syncthreads();
        sh[tid] += v;
        __syncthreads();
    }
    int run = sh[tid] - local;
    for (int i = base; i < lim; i++) {
        int c = g_cursor[i];
        g_rowptr[i] = run;
        g_cursor[i] = run;
        g_dinv[i] = rsqrtf((float)c + 1.0f);
        run += c;
    }
    if (tid == 1023) g_rowptr[NN] = NE;
}

__global__ void k_fill(const int* __restrict__ src, const int* __restrict__ dst) {
    int e = blockIdx.x * blockDim.x + threadIdx.x;
    if (e < NE) {
        int pos = atomicAdd(&g_cursor[dst[e]], 1);
        g_csrc[pos] = src[e];
    }
}

// ---------------- GEMM: (BN+ReLU on input if apply_bn) @ W, store hw*dinv[row] ----------------
// 512 threads, 128 rows/block. Thread t -> rows [(t>>3)*2, +2), cols [(t&7)*8, +8)
// 16 accumulators/thread -> ~38 regs -> 3 CTAs/SM (48 warps) for latency hiding.
#define GEMM_ROWS 128
#define GEMM_SMEM ((DD * DD + GEMM_ROWS * 65) * (int)sizeof(float))
__global__ __launch_bounds__(512, 3) void k_gemm(const float* __restrict__ hin,
                                                 const float* __restrict__ W,
                                                 const float* __restrict__ gamma,
                                                 const float* __restrict__ beta,
                                                 const float* __restrict__ stats,
                                                 int apply_bn) {
    extern __shared__ float dyn[];
    float* ws = dyn;                 // [DD*DD]
    float* hs = dyn + DD * DD;       // [GEMM_ROWS*65]
    __shared__ float sc[DD], mn[DD], bt[DD];
    int tid = threadIdx.x;
    int rowBase = blockIdx.x * GEMM_ROWS;

    if (apply_bn && tid < DD) {
        float mean = stats[tid] * (1.0f / NN);
        float var  = stats[DD + tid] * (1.0f / NN) - mean * mean;
        sc[tid] = gamma[tid] * rsqrtf(var + BN_EPS);
        mn[tid] = mean;
        bt[tid] = beta[tid];
    }
    for (int i = tid; i < DD * DD / 4; i += 512)
        ((float4*)ws)[i] = ((const float4*)W)[i];
    __syncthreads();

    for (int i = tid; i < GEMM_ROWS * 16; i += 512) {
        int r = i >> 4, c4 = (i & 15) << 2;
        int gr = rowBase + r;
        float4 v = (gr < NN) ? *(const float4*)&hin[gr * DD + c4]
                             : make_float4(0.f, 0.f, 0.f, 0.f);
        if (apply_bn) {
            v.x = fmaxf(fmaf(v.x - mn[c4 + 0], sc[c4 + 0], bt[c4 + 0]), 0.f);
            v.y = fmaxf(fmaf(v.y - mn[c4 + 1], sc[c4 + 1], bt[c4 + 1]), 0.f);
            v.z = fmaxf(fmaf(v.z - mn[c4 + 2], sc[c4 + 2], bt[c4 + 2]), 0.f);
            v.w = fmaxf(fmaf(v.w - mn[c4 + 3], sc[c4 + 3], bt[c4 + 3]), 0.f);
        }
        hs[r * 65 + c4 + 0] = v.x;
        hs[r * 65 + c4 + 1] = v.y;
        hs[r * 65 + c4 + 2] = v.z;
        hs[r * 65 + c4 + 3] = v.w;
    }
    __syncthreads();

    int r0 = (tid >> 3) << 1;        // 2 rows per thread (64 row groups)
    int c0 = (tid & 7) << 3;         // 8 cols per thread (8 col groups)
    float acc[2][8];
#pragma unroll
    for (int i = 0; i < 2; i++)
#pragma unroll
        for (int c = 0; c < 8; c++) acc[i][c] = 0.f;

    for (int k = 0; k < DD; k++) {
        const float4* w4 = (const float4*)&ws[k * DD + c0];
        float4 w0 = w4[0], w1 = w4[1];
#pragma unroll
        for (int i = 0; i < 2; i++) {
            float hv = hs[(r0 + i) * 65 + k];
            acc[i][0] = fmaf(hv, w0.x, acc[i][0]);
            acc[i][1] = fmaf(hv, w0.y, acc[i][1]);
            acc[i][2] = fmaf(hv, w0.z, acc[i][2]);
            acc[i][3] = fmaf(hv, w0.w, acc[i][3]);
            acc[i][4] = fmaf(hv, w1.x, acc[i][4]);
            acc[i][5] = fmaf(hv, w1.y, acc[i][5]);
            acc[i][6] = fmaf(hv, w1.z, acc[i][6]);
            acc[i][7] = fmaf(hv, w1.w, acc[i][7]);
        }
    }

#pragma unroll
    for (int i = 0; i < 2; i++) {
        int gr = rowBase + r0 + i;
        if (gr < NN) {
            float di = g_dinv[gr];
            float* dstp = &g_hw[gr * DD + c0];
#pragma unroll
            for (int j = 0; j < 2; j++) {
                float4 o;
                o.x = acc[i][4 * j + 0] * di;
                o.y = acc[i][4 * j + 1] * di;
                o.z = acc[i][4 * j + 2] * di;
                o.w = acc[i][4 * j + 3] * di;
                *(float4*)(dstp + 4 * j) = o;
            }
        }
    }
}

// ---------------- CSR gather aggregation + fused BN stats ----------------
__global__ __launch_bounds__(256) void k_aggr(const float* __restrict__ bias,
                                              float* __restrict__ stats) {
    int tid = threadIdx.x;
    int lane = tid & 31;
    int wid = tid >> 5;
    int epar = lane >> 4;
    int c4 = (lane & 15) << 2;

    float s1x = 0.f, s1y = 0.f, s1z = 0.f, s1w = 0.f;
    float s2x = 0.f, s2y = 0.f, s2z = 0.f, s2w = 0.f;

    for (int n = blockIdx.x * 8 + wid; n < NN; n += gridDim.x * 8) {
        int beg = g_rowptr[n];
        int end = g_rowptr[n + 1];
        float4 a = make_float4(0.f, 0.f, 0.f, 0.f);

        int j = beg + epar;
        for (; j + 6 < end; j += 8) {
            int s0 = __ldg(&g_csrc[j]);
            int s1i = __ldg(&g_csrc[j + 2]);
            int s2i = __ldg(&g_csrc[j + 4]);
            int s3i = __ldg(&g_csrc[j + 6]);
            float4 v0 = __ldg((const float4*)&g_hw[s0 * DD + c4]);
            float4 v1 = __ldg((const float4*)&g_hw[s1i * DD + c4]);
            float4 v2 = __ldg((const float4*)&g_hw[s2i * DD + c4]);
            float4 v3 = __ldg((const float4*)&g_hw[s3i * DD + c4]);
            a = f4add(a, f4add(f4add(v0, v1), f4add(v2, v3)));
        }
        for (; j < end; j += 2) {
            int s = __ldg(&g_csrc[j]);
            a = f4add(a, __ldg((const float4*)&g_hw[s * DD + c4]));
        }

        a.x += __shfl_xor_sync(0xffffffffu, a.x, 16);
        a.y += __shfl_xor_sync(0xffffffffu, a.y, 16);
        a.z += __shfl_xor_sync(0xffffffffu, a.z, 16);
        a.w += __shfl_xor_sync(0xffffffffu, a.w, 16);

        if (epar == 0) {
            float4 self = *(const float4*)&g_hw[n * DD + c4];
            a = f4add(a, self);
            float di = g_dinv[n];
            float4 bv = *(const float4*)&bias[c4];
            a.x = fmaf(a.x, di, bv.x);
            a.y = fmaf(a.y, di, bv.y);
            a.z = fmaf(a.z, di, bv.z);
            a.w = fmaf(a.w, di, bv.w);
            *(float4*)&g_acc[n * DD + c4] = a;

            s1x += a.x; s1y += a.y; s1z += a.z; s1w += a.w;
            s2x += a.x * a.x; s2y += a.y * a.y; s2z += a.z * a.z; s2w += a.w * a.w;
        }
    }

    __shared__ float ssum[2 * DD];
    if (tid < 2 * DD) ssum[tid] = 0.f;
    __syncthreads();
    if (epar == 0) {
        atomicAdd(&ssum[c4 + 0], s1x); atomicAdd(&ssum[c4 + 1], s1y);
        atomicAdd(&ssum[c4 + 2], s1z); atomicAdd(&ssum[c4 + 3], s1w);
        atomicAdd(&ssum[DD + c4 + 0], s2x); atomicAdd(&ssum[DD + c4 + 1], s2y);
        atomicAdd(&ssum[DD + c4 + 2], s2z); atomicAdd(&ssum[DD + c4 + 3], s2w);
    }
    __syncthreads();
    if (tid < 2 * DD) atomicAdd(&stats[tid], ssum[tid]);
}

// ---------------- final BN+ReLU fused into global add pool ----------------
__global__ __launch_bounds__(256) void k_poolbn(const int* __restrict__ batch,
                                                const float* __restrict__ gamma,
                                                const float* __restrict__ beta,
                                                const float* __restrict__ stats) {
    __shared__ float sc[DD], mn[DD], bt[DD];
    int tid = threadIdx.x;
    if (tid < DD) {
        float mean = stats[tid] * (1.0f / NN);
        float var  = stats[DD + tid] * (1.0f / NN) - mean * mean;
        sc[tid] = gamma[tid] * rsqrtf(var + BN_EPS);
        mn[tid] = mean;
        bt[tid] = beta[tid];
    }
    __syncthreads();
    int t = blockIdx.x * blockDim.x + tid;
    int n = t >> 4;
    if (n >= NN) return;
    int c4 = (t & 15) << 2;
    int g = batch[n];
    float4 v = *(const float4*)&g_acc[n * DD + c4];
    v.x = fmaxf(fmaf(v.x - mn[c4 + 0], sc[c4 + 0], bt[c4 + 0]), 0.f);
    v.y = fmaxf(fmaf(v.y - mn[c4 + 1], sc[c4 + 1], bt[c4 + 1]), 0.f);
    v.z = fmaxf(fmaf(v.z - mn[c4 + 2], sc[c4 + 2], bt[c4 + 2]), 0.f);
    v.w = fmaxf(fmaf(v.w - mn[c4 + 3], sc[c4 + 3], bt[c4 + 3]), 0.f);
    atomicAdd((float4*)&g_pooled[g * DD + c4], v);
}

// ---------------- MLP head ----------------
__global__ __launch_bounds__(256) void k_mlp(const float* __restrict__ w1, const float* __restrict__ b1,
                                             const float* __restrict__ w2, const float* __restrict__ b2,
                                             const float* __restrict__ w3, const float* __restrict__ b3,
                                             float* __restrict__ out) {
    __shared__ float ws[DD * DD];
    __shared__ float zs[64 * 65];
    __shared__ float w3s[DD];
    int tid = threadIdx.x;
    int rowBase = blockIdx.x * 64;
    int r = tid >> 2;
    int c0 = (tid & 3) << 4;
    int gr = rowBase + r;

    for (int i = tid; i < DD * DD / 4; i += 256)
        ((float4*)ws)[i] = ((const float4*)w1)[i];
    if (tid < DD) w3s[tid] = w3[tid];
    __syncthreads();

    float acc[16];
#pragma unroll
    for (int c = 0; c < 16; c++) acc[c] = b1[c0 + c];
    for (int k = 0; k < DD; k++) {
        float pv = g_pooled[gr * DD + k];
        const float4* w4 = (const float4*)&ws[k * DD + c0];
        float4 a = w4[0], b = w4[1], cc = w4[2], d = w4[3];
        acc[0]  = fmaf(pv, a.x, acc[0]);   acc[1]  = fmaf(pv, a.y, acc[1]);
        acc[2]  = fmaf(pv, a.z, acc[2]);   acc[3]  = fmaf(pv, a.w, acc[3]);
        acc[4]  = fmaf(pv, b.x, acc[4]);   acc[5]  = fmaf(pv, b.y, acc[5]);
        acc[6]  = fmaf(pv, b.z, acc[6]);   acc[7]  = fmaf(pv, b.w, acc[7]);
        acc[8]  = fmaf(pv, cc.x, acc[8]);  acc[9]  = fmaf(pv, cc.y, acc[9]);
        acc[10] = fmaf(pv, cc.z, acc[10]); acc[11] = fmaf(pv, cc.w, acc[11]);
        acc[12] = fmaf(pv, d.x, acc[12]);  acc[13] = fmaf(pv, d.y, acc[13]);
        acc[14] = fmaf(pv, d.z, acc[14]);  acc[15] = fmaf(pv, d.w, acc[15]);
    }
#pragma unroll
    for (int c = 0; c < 16; c++) zs[r * 65 + c0 + c] = fmaxf(acc[c], 0.f);
    __syncthreads();

    for (int i = tid; i < DD * DD / 4; i += 256)
        ((float4*)ws)[i] = ((const float4*)w2)[i];
    __syncthreads();

#pragma unroll
    for (int c = 0; c < 16; c++) acc[c] = b2[c0 + c];
    for (int k = 0; k < DD; k++) {
        float zv = zs[r * 65 + k];
        const float4* w4 = (const float4*)&ws[k * DD + c0];
        float4 a = w4[0], b = w4[1], cc = w4[2], d = w4[3];
        acc[0]  = fmaf(zv, a.x, acc[0]);   acc[1]  = fmaf(zv, a.y, acc[1]);
        acc[2]  = fmaf(zv, a.z, acc[2]);   acc[3]  = fmaf(zv, a.w, acc[3]);
        acc[4]  = fmaf(zv, b.x, acc[4]);   acc[5]  = fmaf(zv, b.y, acc[5]);
        acc[6]  = fmaf(zv, b.z, acc[6]);   acc[7]  = fmaf(zv, b.w, acc[7]);
        acc[8]  = fmaf(zv, cc.x, acc[8]);  acc[9]  = fmaf(zv, cc.y, acc[9]);
        acc[10] = fmaf(zv, cc.z, acc[10]); acc[11] = fmaf(zv, cc.w, acc[11]);
        acc[12] = fmaf(zv, d.x, acc[12]);  acc[13] = fmaf(zv, d.y, acc[13]);
        acc[14] = fmaf(zv, d.z, acc[14]);  acc[15] = fmaf(zv, d.w, acc[15]);
    }
    __syncthreads();
#pragma unroll
    for (int c = 0; c < 16; c++) zs[r * 65 + c0 + c] = fmaxf(acc[c], 0.f);
    __syncthreads();

    if ((tid & 3) == 0) {
        float s = b3[0];
        for (int k = 0; k < DD; k++) s = fmaf(zs[r * 65 + k], w3s[k], s);
        out[gr] = s;
    }
}

// ---------------- launch ----------------
extern "C" void kernel_launch(void* const* d_in, const int* in_sizes, int n_in,
                              void* d_out, int out_size) {
    const float* x      = (const float*)d_in[0];
    const int*   ei     = (const int*)d_in[1];
    const int*   batch  = (const int*)d_in[2];
    const float* Ws     = (const float*)d_in[3];
    const float* bs     = (const float*)d_in[4];
    const float* gamma  = (const float*)d_in[5];
    const float* beta   = (const float*)d_in[6];
    const float* w1     = (const float*)d_in[7];
    const float* b1     = (const float*)d_in[8];
    const float* w2     = (const float*)d_in[9];
    const float* b2     = (const float*)d_in[10];
    const float* w3     = (const float*)d_in[11];
    const float* b3     = (const float*)d_in[12];
    float* out = (float*)d_out;

    const int* src = ei;
    const int* dst = ei + NE;

    void *p_cursor = nullptr, *p_stats = nullptr, *p_pooled = nullptr, *p_acc = nullptr;
    cudaGetSymbolAddress(&p_cursor, g_cursor);
    cudaGetSymbolAddress(&p_stats, g_stats);
    cudaGetSymbolAddress(&p_pooled, g_pooled);
    cudaGetSymbolAddress(&p_acc, g_acc);
    float* stats = (float*)p_stats;

    cudaFuncSetAttribute(k_gemm, cudaFuncAttributeMaxDynamicSharedMemorySize, GEMM_SMEM);

    // CSR build (once per launch)
    cudaMemsetAsync(p_cursor, 0, NN * sizeof(int), 0);
    cudaMemsetAsync(p_stats, 0, NL * 2 * DD * sizeof(float), 0);
    cudaMemsetAsync(p_pooled, 0, NG * DD * sizeof(float), 0);
    k_hist<<<(NE + 255) / 256, 256>>>(dst);
    k_scan<<<1, 1024>>>();
    k_fill<<<(NE + 255) / 256, 256>>>(src, dst);

    const float* hin = x;
    for (int l = 0; l < NL; l++) {
        k_gemm<<<(NN + GEMM_ROWS - 1) / GEMM_ROWS, 512, GEMM_SMEM>>>(
            hin, Ws + l * DD * DD,
            gamma + (l - 1) * DD, beta + (l - 1) * DD,
            stats + (l - 1) * 2 * DD, l > 0);
        k_aggr<<<2048, 256>>>(bs + l * DD, stats + l * 2 * DD);
        hin = (const float*)p_acc;
    }

    k_poolbn<<<(NN * 16 + 255) / 256, 256>>>(batch, gamma + 3 * DD, beta + 3 * DD,
                                             stats + 3 * 2 * DD);
    k_mlp<<<NG / 64, 256>>>(w1, b1, w2, b2, w3, b3, out);
}

// round 11
// speedup vs baseline: 1.1308x; 1.1308x over previous
#include <cuda_runtime.h>
#include <cuda_bf16.h>

#define NN 50000
#define NE 800000
#define DD 64
#define NG 1024
#define NL 4
#define BN_EPS 1e-5f

// ---------------- scratch (device globals) ----------------
__device__ __align__(16) float g_hw[NN * DD];         // (h @ W) * dinv[row]
__device__ __align__(16) float g_acc[NN * DD];        // pre-BN accumulator
__device__ __align__(16) float g_dinv[NN];
__device__ __align__(16) float g_stats[NL * 2 * DD];  // per-layer [sum, sumsq]
__device__ __align__(16) float g_pooled[NG * DD];
__device__ int g_rowptr[NN + 1];
__device__ int g_cursor[NN];
__device__ int g_csrc[NE];

__device__ __forceinline__ float4 f4add(float4 a, float4 b) {
    a.x += b.x; a.y += b.y; a.z += b.z; a.w += b.w; return a;
}

// ---------------- CSR build ----------------
__global__ void k_hist(const int* __restrict__ dst) {
    int e = blockIdx.x * blockDim.x + threadIdx.x;
    if (e < NE) atomicAdd(&g_cursor[dst[e]], 1);
}

__global__ __launch_bounds__(1024) void k_scan() {
    const int CH = (NN + 1023) / 1024;  // 49
    int tid = threadIdx.x;
    int base = tid * CH;
    int lim = min(base + CH, NN);
    int local = 0;
    for (int i = base; i < lim; i++) local += g_cursor[i];

    __shared__ int sh[1024];
    sh[tid] = local;
    __syncthreads();
    for (int off = 1; off < 1024; off <<= 1) {
        int v = (tid >= off) ? sh[tid - off] : 0;
        __syncthreads();
        sh[tid] += v;
        __syncthreads();
    }
    int run = sh[tid] - local;
    for (int i = base; i < lim; i++) {
        int c = g_cursor[i];
        g_rowptr[i] = run;
        g_cursor[i] = run;
        g_dinv[i] = rsqrtf((float)c + 1.0f);
        run += c;
    }
    if (tid == 1023) g_rowptr[NN] = NE;
}

__global__ void k_fill(const int* __restrict__ src, const int* __restrict__ dst) {
    int e = blockIdx.x * blockDim.x + threadIdx.x;
    if (e < NE) {
        int pos = atomicAdd(&g_cursor[dst[e]], 1);
        g_csrc[pos] = src[e];
    }
}

// ---------------- GEMM: (BN+ReLU on input if apply_bn) @ W, store hw*dinv[row] ----------------
// 256 threads, 128 rows/block. Thread t -> rows [(t>>3)*4, +4), cols [(t&7)*8, +8)
// 32 accumulators/thread, 1.5 B LDS per FMA; unroll-2 k-loop to pipeline LDS under FFMA.
#define GEMM_ROWS 128
#define GEMM_SMEM ((DD * DD + GEMM_ROWS * 65) * (int)sizeof(float))
__global__ __launch_bounds__(256, 3) void k_gemm(const float* __restrict__ hin,
                                                 const float* __restrict__ W,
                                                 const float* __restrict__ gamma,
                                                 const float* __restrict__ beta,
                                                 const float* __restrict__ stats,
                                                 int apply_bn) {
    extern __shared__ float dyn[];
    float* ws = dyn;                 // [DD*DD]
    float* hs = dyn + DD * DD;       // [GEMM_ROWS*65]
    __shared__ float sc[DD], mn[DD], bt[DD];
    int tid = threadIdx.x;
    int rowBase = blockIdx.x * GEMM_ROWS;

    if (apply_bn && tid < DD) {
        float mean = stats[tid] * (1.0f / NN);
        float var  = stats[DD + tid] * (1.0f / NN) - mean * mean;
        sc[tid] = gamma[tid] * rsqrtf(var + BN_EPS);
        mn[tid] = mean;
        bt[tid] = beta[tid];
    }
    for (int i = tid; i < DD * DD / 4; i += 256)
        ((float4*)ws)[i] = ((const float4*)W)[i];
    __syncthreads();

    for (int i = tid; i < GEMM_ROWS * 16; i += 256) {
        int r = i >> 4, c4 = (i & 15) << 2;
        int gr = rowBase + r;
        float4 v = (gr < NN) ? *(const float4*)&hin[gr * DD + c4]
                             : make_float4(0.f, 0.f, 0.f, 0.f);
        if (apply_bn) {
            v.x = fmaxf(fmaf(v.x - mn[c4 + 0], sc[c4 + 0], bt[c4 + 0]), 0.f);
            v.y = fmaxf(fmaf(v.y - mn[c4 + 1], sc[c4 + 1], bt[c4 + 1]), 0.f);
            v.z = fmaxf(fmaf(v.z - mn[c4 + 2], sc[c4 + 2], bt[c4 + 2]), 0.f);
            v.w = fmaxf(fmaf(v.w - mn[c4 + 3], sc[c4 + 3], bt[c4 + 3]), 0.f);
        }
        hs[r * 65 + c4 + 0] = v.x;
        hs[r * 65 + c4 + 1] = v.y;
        hs[r * 65 + c4 + 2] = v.z;
        hs[r * 65 + c4 + 3] = v.w;
    }
    __syncthreads();

    int r0 = (tid >> 3) << 2;        // 4 rows per thread (32 row groups)
    int c0 = (tid & 7) << 3;         // 8 cols per thread (8 col groups)
    float acc[4][8];
#pragma unroll
    for (int i = 0; i < 4; i++)
#pragma unroll
        for (int c = 0; c < 8; c++) acc[i][c] = 0.f;

#pragma unroll 2
    for (int k = 0; k < DD; k++) {
        const float4* w4 = (const float4*)&ws[k * DD + c0];
        float4 w0 = w4[0], w1 = w4[1];
#pragma unroll
        for (int i = 0; i < 4; i++) {
            float hv = hs[(r0 + i) * 65 + k];
            acc[i][0] = fmaf(hv, w0.x, acc[i][0]);
            acc[i][1] = fmaf(hv, w0.y, acc[i][1]);
            acc[i][2] = fmaf(hv, w0.z, acc[i][2]);
            acc[i][3] = fmaf(hv, w0.w, acc[i][3]);
            acc[i][4] = fmaf(hv, w1.x, acc[i][4]);
            acc[i][5] = fmaf(hv, w1.y, acc[i][5]);
            acc[i][6] = fmaf(hv, w1.z, acc[i][6]);
            acc[i][7] = fmaf(hv, w1.w, acc[i][7]);
        }
    }

#pragma unroll
    for (int i = 0; i < 4; i++) {
        int gr = rowBase + r0 + i;
        if (gr < NN) {
            float di = g_dinv[gr];
            float* dstp = &g_hw[gr * DD + c0];
#pragma unroll
            for (int j = 0; j < 2; j++) {
                float4 o;
                o.x = acc[i][4 * j + 0] * di;
                o.y = acc[i][4 * j + 1] * di;
                o.z = acc[i][4 * j + 2] * di;
                o.w = acc[i][4 * j + 3] * di;
                *(float4*)(dstp + 4 * j) = o;
            }
        }
    }
}

// ---------------- CSR gather aggregation + fused BN stats ----------------
__global__ __launch_bounds__(256) void k_aggr(const float* __restrict__ bias,
                                              float* __restrict__ stats) {
    int tid = threadIdx.x;
    int lane = tid & 31;
    int wid = tid >> 5;
    int epar = lane >> 4;
    int c4 = (lane & 15) << 2;

    float s1x = 0.f, s1y = 0.f, s1z = 0.f, s1w = 0.f;
    float s2x = 0.f, s2y = 0.f, s2z = 0.f, s2w = 0.f;

    for (int n = blockIdx.x * 8 + wid; n < NN; n += gridDim.x * 8) {
        int beg = g_rowptr[n];
        int end = g_rowptr[n + 1];
        float4 a = make_float4(0.f, 0.f, 0.f, 0.f);

        int j = beg + epar;
        for (; j + 6 < end; j += 8) {
            int s0 = __ldg(&g_csrc[j]);
            int s1i = __ldg(&g_csrc[j + 2]);
            int s2i = __ldg(&g_csrc[j + 4]);
            int s3i = __ldg(&g_csrc[j + 6]);
            float4 v0 = __ldg((const float4*)&g_hw[s0 * DD + c4]);
            float4 v1 = __ldg((const float4*)&g_hw[s1i * DD + c4]);
            float4 v2 = __ldg((const float4*)&g_hw[s2i * DD + c4]);
            float4 v3 = __ldg((const float4*)&g_hw[s3i * DD + c4]);
            a = f4add(a, f4add(f4add(v0, v1), f4add(v2, v3)));
        }
        for (; j < end; j += 2) {
            int s = __ldg(&g_csrc[j]);
            a = f4add(a, __ldg((const float4*)&g_hw[s * DD + c4]));
        }

        a.x += __shfl_xor_sync(0xffffffffu, a.x, 16);
        a.y += __shfl_xor_sync(0xffffffffu, a.y, 16);
        a.z += __shfl_xor_sync(0xffffffffu, a.z, 16);
        a.w += __shfl_xor_sync(0xffffffffu, a.w, 16);

        if (epar == 0) {
            float4 self = *(const float4*)&g_hw[n * DD + c4];
            a = f4add(a, self);
            float di = g_dinv[n];
            float4 bv = *(const float4*)&bias[c4];
            a.x = fmaf(a.x, di, bv.x);
            a.y = fmaf(a.y, di, bv.y);
            a.z = fmaf(a.z, di, bv.z);
            a.w = fmaf(a.w, di, bv.w);
            *(float4*)&g_acc[n * DD + c4] = a;

            s1x += a.x; s1y += a.y; s1z += a.z; s1w += a.w;
            s2x += a.x * a.x; s2y += a.y * a.y; s2z += a.z * a.z; s2w += a.w * a.w;
        }
    }

    __shared__ float ssum[2 * DD];
    if (tid < 2 * DD) ssum[tid] = 0.f;
    __syncthreads();
    if (epar == 0) {
        atomicAdd(&ssum[c4 + 0], s1x); atomicAdd(&ssum[c4 + 1], s1y);
        atomicAdd(&ssum[c4 + 2], s1z); atomicAdd(&ssum[c4 + 3], s1w);
        atomicAdd(&ssum[DD + c4 + 0], s2x); atomicAdd(&ssum[DD + c4 + 1], s2y);
        atomicAdd(&ssum[DD + c4 + 2], s2z); atomicAdd(&ssum[DD + c4 + 3], s2w);
    }
    __syncthreads();
    if (tid < 2 * DD) atomicAdd(&stats[tid], ssum[tid]);
}

// ---------------- final BN+ReLU fused into global add pool ----------------
__global__ __launch_bounds__(256) void k_poolbn(const int* __restrict__ batch,
                                                const float* __restrict__ gamma,
                                                const float* __restrict__ beta,
                                                const float* __restrict__ stats) {
    __shared__ float sc[DD], mn[DD], bt[DD];
    int tid = threadIdx.x;
    if (tid < DD) {
        float mean = stats[tid] * (1.0f / NN);
        float var  = stats[DD + tid] * (1.0f / NN) - mean * mean;
        sc[tid] = gamma[tid] * rsqrtf(var + BN_EPS);
        mn[tid] = mean;
        bt[tid] = beta[tid];
    }
    __syncthreads();
    int t = blockIdx.x * blockDim.x + tid;
    int n = t >> 4;
    if (n >= NN) return;
    int c4 = (t & 15) << 2;
    int g = batch[n];
    float4 v = *(const float4*)&g_acc[n * DD + c4];
    v.x = fmaxf(fmaf(v.x - mn[c4 + 0], sc[c4 + 0], bt[c4 + 0]), 0.f);
    v.y = fmaxf(fmaf(v.y - mn[c4 + 1], sc[c4 + 1], bt[c4 + 1]), 0.f);
    v.z = fmaxf(fmaf(v.z - mn[c4 + 2], sc[c4 + 2], bt[c4 + 2]), 0.f);
    v.w = fmaxf(fmaf(v.w - mn[c4 + 3], sc[c4 + 3], bt[c4 + 3]), 0.f);
    atomicAdd((float4*)&g_pooled[g * DD + c4], v);
}

// ---------------- MLP head ----------------
__global__ __launch_bounds__(256) void k_mlp(const float* __restrict__ w1, const float* __restrict__ b1,
                                             const float* __restrict__ w2, const float* __restrict__ b2,
                                             const float* __restrict__ w3, const float* __restrict__ b3,
                                             float* __restrict__ out) {
    __shared__ float ws[DD * DD];
    __shared__ float zs[64 * 65];
    __shared__ float w3s[DD];
    int tid = threadIdx.x;
    int rowBase = blockIdx.x * 64;
    int r = tid >> 2;
    int c0 = (tid & 3) << 4;
    int gr = rowBase + r;

    for (int i = tid; i < DD * DD / 4; i += 256)
        ((float4*)ws)[i] = ((const float4*)w1)[i];
    if (tid < DD) w3s[tid] = w3[tid];
    __syncthreads();

    float acc[16];
#pragma unroll
    for (int c = 0; c < 16; c++) acc[c] = b1[c0 + c];
    for (int k = 0; k < DD; k++) {
        float pv = g_pooled[gr * DD + k];
        const float4* w4 = (const float4*)&ws[k * DD + c0];
        float4 a = w4[0], b = w4[1], cc = w4[2], d = w4[3];
        acc[0]  = fmaf(pv, a.x, acc[0]);   acc[1]  = fmaf(pv, a.y, acc[1]);
        acc[2]  = fmaf(pv, a.z, acc[2]);   acc[3]  = fmaf(pv, a.w, acc[3]);
        acc[4]  = fmaf(pv, b.x, acc[4]);   acc[5]  = fmaf(pv, b.y, acc[5]);
        acc[6]  = fmaf(pv, b.z, acc[6]);   acc[7]  = fmaf(pv, b.w, acc[7]);
        acc[8]  = fmaf(pv, cc.x, acc[8]);  acc[9]  = fmaf(pv, cc.y, acc[9]);
        acc[10] = fmaf(pv, cc.z, acc[10]); acc[11] = fmaf(pv, cc.w, acc[11]);
        acc[12] = fmaf(pv, d.x, acc[12]);  acc[13] = fmaf(pv, d.y, acc[13]);
        acc[14] = fmaf(pv, d.z, acc[14]);  acc[15] = fmaf(pv, d.w, acc[15]);
    }
#pragma unroll
    for (int c = 0; c < 16; c++) zs[r * 65 + c0 + c] = fmaxf(acc[c], 0.f);
    __syncthreads();

    for (int i = tid; i < DD * DD / 4; i += 256)
        ((float4*)ws)[i] = ((const float4*)w2)[i];
    __syncthreads();

#pragma unroll
    for (int c = 0; c < 16; c++) acc[c] = b2[c0 + c];
    for (int k = 0; k < DD; k++) {
        float zv = zs[r * 65 + k];
        const float4* w4 = (const float4*)&ws[k * DD + c0];
        float4 a = w4[0], b = w4[1], cc = w4[2], d = w4[3];
        acc[0]  = fmaf(zv, a.x, acc[0]);   acc[1]  = fmaf(zv, a.y, acc[1]);
        acc[2]  = fmaf(zv, a.z, acc[2]);   acc[3]  = fmaf(zv, a.w, acc[3]);
        acc[4]  = fmaf(zv, b.x, acc[4]);   acc[5]  = fmaf(zv, b.y, acc[5]);
        acc[6]  = fmaf(zv, b.z, acc[6]);   acc[7]  = fmaf(zv, b.w, acc[7]);
        acc[8]  = fmaf(zv, cc.x, acc[8]);  acc[9]  = fmaf(zv, cc.y, acc[9]);
        acc[10] = fmaf(zv, cc.z, acc[10]); acc[11] = fmaf(zv, cc.w, acc[11]);
        acc[12] = fmaf(zv, d.x, acc[12]);  acc[13] = fmaf(zv, d.y, acc[13]);
        acc[14] = fmaf(zv, d.z, acc[14]);  acc[15] = fmaf(zv, d.w, acc[15]);
    }
    __syncthreads();
#pragma unroll
    for (int c = 0; c < 16; c++) zs[r * 65 + c0 + c] = fmaxf(acc[c], 0.f);
    __syncthreads();

    if ((tid & 3) == 0) {
        float s = b3[0];
        for (int k = 0; k < DD; k++) s = fmaf(zs[r * 65 + k], w3s[k], s);
        out[gr] = s;
    }
}

// ---------------- launch ----------------
extern "C" void kernel_launch(void* const* d_in, const int* in_sizes, int n_in,
                              void* d_out, int out_size) {
    const float* x      = (const float*)d_in[0];
    const int*   ei     = (const int*)d_in[1];
    const int*   batch  = (const int*)d_in[2];
    const float* Ws     = (const float*)d_in[3];
    const float* bs     = (const float*)d_in[4];
    const float* gamma  = (const float*)d_in[5];
    const float* beta   = (const float*)d_in[6];
    const float* w1     = (const float*)d_in[7];
    const float* b1     = (const float*)d_in[8];
    const float* w2     = (const float*)d_in[9];
    const float* b2     = (const float*)d_in[10];
    const float* w3     = (const float*)d_in[11];
    const float* b3     = (const float*)d_in[12];
    float* out = (float*)d_out;

    const int* src = ei;
    const int* dst = ei + NE;

    void *p_cursor = nullptr, *p_stats = nullptr, *p_pooled = nullptr, *p_acc = nullptr;
    cudaGetSymbolAddress(&p_cursor, g_cursor);
    cudaGetSymbolAddress(&p_stats, g_stats);
    cudaGetSymbolAddress(&p_pooled, g_pooled);
    cudaGetSymbolAddress(&p_acc, g_acc);
    float* stats = (float*)p_stats;

    cudaFuncSetAttribute(k_gemm, cudaFuncAttributeMaxDynamicSharedMemorySize, GEMM_SMEM);

    // CSR build (once per launch)
    cudaMemsetAsync(p_cursor, 0, NN * sizeof(int), 0);
    cudaMemsetAsync(p_stats, 0, NL * 2 * DD * sizeof(float), 0);
    cudaMemsetAsync(p_pooled, 0, NG * DD * sizeof(float), 0);
    k_hist<<<(NE + 255) / 256, 256>>>(dst);
    k_scan<<<1, 1024>>>();
    k_fill<<<(NE + 255) / 256, 256>>>(src, dst);

    const float* hin = x;
    for (int l = 0; l < NL; l++) {
        k_gemm<<<(NN + GEMM_ROWS - 1) / GEMM_ROWS, 256, GEMM_SMEM>>>(
            hin, Ws + l * DD * DD,
            gamma + (l - 1) * DD, beta + (l - 1) * DD,
            stats + (l - 1) * 2 * DD, l > 0);
        k_aggr<<<2048, 256>>>(bs + l * DD, stats + l * 2 * DD);
        hin = (const float*)p_acc;
    }

    k_poolbn<<<(NN * 16 + 255) / 256, 256>>>(batch, gamma + 3 * DD, beta + 3 * DD,
                                             stats + 3 * 2 * DD);
    k_mlp<<<NG / 64, 256>>>(w1, b1, w2, b2, w3, b3, out);
}

// round 12
// speedup vs baseline: 1.6081x; 1.4222x over previous
#include <cuda_runtime.h>
#include <cuda_bf16.h>

#define NN 50000
#define NE 800000
#define DD 64
#define NG 1024
#define NL 4
#define BN_EPS 1e-5f
#define NB_SCAN 196   // ceil(NN/256)

// ---------------- scratch (device globals) ----------------
__device__ __align__(16) float g_hw[NN * DD];         // (h @ W) * dinv[row]
__device__ __align__(16) float g_acc[NN * DD];        // pre-BN accumulator
__device__ __align__(16) float g_dinv[NN];
__device__ __align__(16) float g_stats[NL * 2 * DD];  // per-layer [sum, sumsq]
__device__ __align__(16) float g_pooled[NG * DD];
__device__ int g_rowptr[NN + 1];
__device__ int g_cursor[NN];                          // counts, then fill cursors; zeroed by k_mlp
__device__ int g_csrc[NE];
__device__ int g_bsum[256];                           // per-block count sums

__device__ __forceinline__ float4 f4add(float4 a, float4 b) {
    a.x += b.x; a.y += b.y; a.z += b.z; a.w += b.w; return a;
}

// ---------------- CSR build ----------------
__global__ void k_hist(const int* __restrict__ dst) {
    int e = blockIdx.x * blockDim.x + threadIdx.x;
    if (e < NE) atomicAdd(&g_cursor[dst[e]], 1);
}

// per-block sums of counts (coalesced)
__global__ __launch_bounds__(256) void k_bsum() {
    __shared__ int sh[256];
    int tid = threadIdx.x;
    int i = blockIdx.x * 256 + tid;
    int c = (i < NN) ? g_cursor[i] : 0;
    sh[tid] = c;
    __syncthreads();
    for (int off = 128; off > 0; off >>= 1) {
        if (tid < off) sh[tid] += sh[tid + off];
        __syncthreads();
    }
    if (tid == 0) g_bsum[blockIdx.x] = sh[0];
}

// block prefix (inline reduce of bsum[0..b-1]) + intra-block scan -> rowptr/cursor/dinv
__global__ __launch_bounds__(256) void k_apply() {
    __shared__ int sh[256];
    int tid = threadIdx.x;
    int b = blockIdx.x;
    int i = b * 256 + tid;

    // exclusive block prefix: sum of bsum[0..b-1]
    int bv = (tid < b) ? g_bsum[tid] : 0;   // b <= 195 < 256
    sh[tid] = bv;
    __syncthreads();
    for (int off = 128; off > 0; off >>= 1) {
        if (tid < off) sh[tid] += sh[tid + off];
        __syncthreads();
    }
    int bpre = sh[0];
    __syncthreads();

    // intra-block inclusive scan of counts
    int c = (i < NN) ? g_cursor[i] : 0;
    sh[tid] = c;
    __syncthreads();
    for (int off = 1; off < 256; off <<= 1) {
        int v = (tid >= off) ? sh[tid - off] : 0;
        __syncthreads();
        sh[tid] += v;
        __syncthreads();
    }
    int excl = sh[tid] - c + bpre;
    if (i < NN) {
        g_rowptr[i] = excl;
        g_cursor[i] = excl;
        g_dinv[i] = rsqrtf((float)c + 1.0f);
    }
    if (i == NN - 1) g_rowptr[NN] = NE;
}

__global__ void k_fill(const int* __restrict__ src, const int* __restrict__ dst) {
    int e = blockIdx.x * blockDim.x + threadIdx.x;
    if (e < NE) {
        int pos = atomicAdd(&g_cursor[dst[e]], 1);
        g_csrc[pos] = src[e];
    }
}

// ---------------- GEMM: (BN+ReLU on input if apply_bn) @ W, store hw*dinv[row] ----------------
// 256 threads, 128 rows/block. Thread t -> rows [(t>>3)*4, +4), cols [(t&7)*8, +8)
// Also zeroes this layer's stats slot (replaces memset node).
#define GEMM_ROWS 128
#define GEMM_SMEM ((DD * DD + GEMM_ROWS * 65) * (int)sizeof(float))
__global__ __launch_bounds__(256, 3) void k_gemm(const float* __restrict__ hin,
                                                 const float* __restrict__ W,
                                                 const float* __restrict__ gamma,
                                                 const float* __restrict__ beta,
                                                 const float* __restrict__ stats,
                                                 float* __restrict__ stats_out,
                                                 int apply_bn) {
    extern __shared__ float dyn[];
    float* ws = dyn;                 // [DD*DD]
    float* hs = dyn + DD * DD;       // [GEMM_ROWS*65]
    __shared__ float sc[DD], mn[DD], bt[DD];
    int tid = threadIdx.x;
    int rowBase = blockIdx.x * GEMM_ROWS;

    if (blockIdx.x == 0 && tid < 2 * DD) stats_out[tid] = 0.f;

    if (apply_bn && tid < DD) {
        float mean = stats[tid] * (1.0f / NN);
        float var  = stats[DD + tid] * (1.0f / NN) - mean * mean;
        sc[tid] = gamma[tid] * rsqrtf(var + BN_EPS);
        mn[tid] = mean;
        bt[tid] = beta[tid];
    }
    for (int i = tid; i < DD * DD / 4; i += 256)
        ((float4*)ws)[i] = ((const float4*)W)[i];
    __syncthreads();

    for (int i = tid; i < GEMM_ROWS * 16; i += 256) {
        int r = i >> 4, c4 = (i & 15) << 2;
        int gr = rowBase + r;
        float4 v = (gr < NN) ? *(const float4*)&hin[gr * DD + c4]
                             : make_float4(0.f, 0.f, 0.f, 0.f);
        if (apply_bn) {
            v.x = fmaxf(fmaf(v.x - mn[c4 + 0], sc[c4 + 0], bt[c4 + 0]), 0.f);
            v.y = fmaxf(fmaf(v.y - mn[c4 + 1], sc[c4 + 1], bt[c4 + 1]), 0.f);
            v.z = fmaxf(fmaf(v.z - mn[c4 + 2], sc[c4 + 2], bt[c4 + 2]), 0.f);
            v.w = fmaxf(fmaf(v.w - mn[c4 + 3], sc[c4 + 3], bt[c4 + 3]), 0.f);
        }
        hs[r * 65 + c4 + 0] = v.x;
        hs[r * 65 + c4 + 1] = v.y;
        hs[r * 65 + c4 + 2] = v.z;
        hs[r * 65 + c4 + 3] = v.w;
    }
    __syncthreads();

    int r0 = (tid >> 3) << 2;        // 4 rows per thread
    int c0 = (tid & 7) << 3;         // 8 cols per thread
    float acc[4][8];
#pragma unroll
    for (int i = 0; i < 4; i++)
#pragma unroll
        for (int c = 0; c < 8; c++) acc[i][c] = 0.f;

#pragma unroll 2
    for (int k = 0; k < DD; k++) {
        const float4* w4 = (const float4*)&ws[k * DD + c0];
        float4 w0 = w4[0], w1 = w4[1];
#pragma unroll
        for (int i = 0; i < 4; i++) {
            float hv = hs[(r0 + i) * 65 + k];
            acc[i][0] = fmaf(hv, w0.x, acc[i][0]);
            acc[i][1] = fmaf(hv, w0.y, acc[i][1]);
            acc[i][2] = fmaf(hv, w0.z, acc[i][2]);
            acc[i][3] = fmaf(hv, w0.w, acc[i][3]);
            acc[i][4] = fmaf(hv, w1.x, acc[i][4]);
            acc[i][5] = fmaf(hv, w1.y, acc[i][5]);
            acc[i][6] = fmaf(hv, w1.z, acc[i][6]);
            acc[i][7] = fmaf(hv, w1.w, acc[i][7]);
        }
    }

#pragma unroll
    for (int i = 0; i < 4; i++) {
        int gr = rowBase + r0 + i;
        if (gr < NN) {
            float di = g_dinv[gr];
            float* dstp = &g_hw[gr * DD + c0];
#pragma unroll
            for (int j = 0; j < 2; j++) {
                float4 o;
                o.x = acc[i][4 * j + 0] * di;
                o.y = acc[i][4 * j + 1] * di;
                o.z = acc[i][4 * j + 2] * di;
                o.w = acc[i][4 * j + 3] * di;
                *(float4*)(dstp + 4 * j) = o;
            }
        }
    }
}

// ---------------- CSR gather aggregation + fused BN stats ----------------
__global__ __launch_bounds__(256) void k_aggr(const float* __restrict__ bias,
                                              float* __restrict__ stats) {
    int tid = threadIdx.x;
    int lane = tid & 31;
    int wid = tid >> 5;
    int epar = lane >> 4;
    int c4 = (lane & 15) << 2;

    float s1x = 0.f, s1y = 0.f, s1z = 0.f, s1w = 0.f;
    float s2x = 0.f, s2y = 0.f, s2z = 0.f, s2w = 0.f;

    for (int n = blockIdx.x * 8 + wid; n < NN; n += gridDim.x * 8) {
        int beg = g_rowptr[n];
        int end = g_rowptr[n + 1];
        float4 a = make_float4(0.f, 0.f, 0.f, 0.f);

        int j = beg + epar;
        for (; j + 6 < end; j += 8) {
            int s0 = __ldg(&g_csrc[j]);
            int s1i = __ldg(&g_csrc[j + 2]);
            int s2i = __ldg(&g_csrc[j + 4]);
            int s3i = __ldg(&g_csrc[j + 6]);
            float4 v0 = __ldg((const float4*)&g_hw[s0 * DD + c4]);
            float4 v1 = __ldg((const float4*)&g_hw[s1i * DD + c4]);
            float4 v2 = __ldg((const float4*)&g_hw[s2i * DD + c4]);
            float4 v3 = __ldg((const float4*)&g_hw[s3i * DD + c4]);
            a = f4add(a, f4add(f4add(v0, v1), f4add(v2, v3)));
        }
        for (; j < end; j += 2) {
            int s = __ldg(&g_csrc[j]);
            a = f4add(a, __ldg((const float4*)&g_hw[s * DD + c4]));
        }

        a.x += __shfl_xor_sync(0xffffffffu, a.x, 16);
        a.y += __shfl_xor_sync(0xffffffffu, a.y, 16);
        a.z += __shfl_xor_sync(0xffffffffu, a.z, 16);
        a.w += __shfl_xor_sync(0xffffffffu, a.w, 16);

        if (epar == 0) {
            float4 self = *(const float4*)&g_hw[n * DD + c4];
            a = f4add(a, self);
            float di = g_dinv[n];
            float4 bv = *(const float4*)&bias[c4];
            a.x = fmaf(a.x, di, bv.x);
            a.y = fmaf(a.y, di, bv.y);
            a.z = fmaf(a.z, di, bv.z);
            a.w = fmaf(a.w, di, bv.w);
            *(float4*)&g_acc[n * DD + c4] = a;

            s1x += a.x; s1y += a.y; s1z += a.z; s1w += a.w;
            s2x += a.x * a.x; s2y += a.y * a.y; s2z += a.z * a.z; s2w += a.w * a.w;
        }
    }

    __shared__ float ssum[2 * DD];
    if (tid < 2 * DD) ssum[tid] = 0.f;
    __syncthreads();
    if (epar == 0) {
        atomicAdd(&ssum[c4 + 0], s1x); atomicAdd(&ssum[c4 + 1], s1y);
        atomicAdd(&ssum[c4 + 2], s1z); atomicAdd(&ssum[c4 + 3], s1w);
        atomicAdd(&ssum[DD + c4 + 0], s2x); atomicAdd(&ssum[DD + c4 + 1], s2y);
        atomicAdd(&ssum[DD + c4 + 2], s2z); atomicAdd(&ssum[DD + c4 + 3], s2w);
    }
    __syncthreads();
    if (tid < 2 * DD) atomicAdd(&stats[tid], ssum[tid]);
}

// ---------------- final BN+ReLU fused into global add pool ----------------
__global__ __launch_bounds__(256) void k_poolbn(const int* __restrict__ batch,
                                                const float* __restrict__ gamma,
                                                const float* __restrict__ beta,
                                                const float* __restrict__ stats) {
    __shared__ float sc[DD], mn[DD], bt[DD];
    int tid = threadIdx.x;
    if (tid < DD) {
        float mean = stats[tid] * (1.0f / NN);
        float var  = stats[DD + tid] * (1.0f / NN) - mean * mean;
        sc[tid] = gamma[tid] * rsqrtf(var + BN_EPS);
        mn[tid] = mean;
        bt[tid] = beta[tid];
    }
    __syncthreads();
    int t = blockIdx.x * blockDim.x + tid;
    int n = t >> 4;
    if (n >= NN) return;
    int c4 = (t & 15) << 2;
    int g = batch[n];
    float4 v = *(const float4*)&g_acc[n * DD + c4];
    v.x = fmaxf(fmaf(v.x - mn[c4 + 0], sc[c4 + 0], bt[c4 + 0]), 0.f);
    v.y = fmaxf(fmaf(v.y - mn[c4 + 1], sc[c4 + 1], bt[c4 + 1]), 0.f);
    v.z = fmaxf(fmaf(v.z - mn[c4 + 2], sc[c4 + 2], bt[c4 + 2]), 0.f);
    v.w = fmaxf(fmaf(v.w - mn[c4 + 3], sc[c4 + 3], bt[c4 + 3]), 0.f);
    atomicAdd((float4*)&g_pooled[g * DD + c4], v);
}

// ---------------- MLP head (also zeroes pooled + cursor for the next run) ----------------
__global__ __launch_bounds__(256) void k_mlp(const float* __restrict__ w1, const float* __restrict__ b1,
                                             const float* __restrict__ w2, const float* __restrict__ b2,
                                             const float* __restrict__ w3, const float* __restrict__ b3,
                                             float* __restrict__ out) {
    __shared__ float ws[DD * DD];
    __shared__ float zs[64 * 65];
    __shared__ float w3s[DD];
    int tid = threadIdx.x;
    int rowBase = blockIdx.x * 64;
    int r = tid >> 2;
    int c0 = (tid & 3) << 4;
    int gr = rowBase + r;

    for (int i = tid; i < DD * DD / 4; i += 256)
        ((float4*)ws)[i] = ((const float4*)w1)[i];
    if (tid < DD) w3s[tid] = w3[tid];
    __syncthreads();

    float acc[16];
#pragma unroll
    for (int c = 0; c < 16; c++) acc[c] = b1[c0 + c];
    for (int k = 0; k < DD; k++) {
        float pv = g_pooled[gr * DD + k];
        const float4* w4 = (const float4*)&ws[k * DD + c0];
        float4 a = w4[0], b = w4[1], cc = w4[2], d = w4[3];
        acc[0]  = fmaf(pv, a.x, acc[0]);   acc[1]  = fmaf(pv, a.y, acc[1]);
        acc[2]  = fmaf(pv, a.z, acc[2]);   acc[3]  = fmaf(pv, a.w, acc[3]);
        acc[4]  = fmaf(pv, b.x, acc[4]);   acc[5]  = fmaf(pv, b.y, acc[5]);
        acc[6]  = fmaf(pv, b.z, acc[6]);   acc[7]  = fmaf(pv, b.w, acc[7]);
        acc[8]  = fmaf(pv, cc.x, acc[8]);  acc[9]  = fmaf(pv, cc.y, acc[9]);
        acc[10] = fmaf(pv, cc.z, acc[10]); acc[11] = fmaf(pv, cc.w, acc[11]);
        acc[12] = fmaf(pv, d.x, acc[12]);  acc[13] = fmaf(pv, d.y, acc[13]);
        acc[14] = fmaf(pv, d.z, acc[14]);  acc[15] = fmaf(pv, d.w, acc[15]);
    }
#pragma unroll
    for (int c = 0; c < 16; c++) zs[r * 65 + c0 + c] = fmaxf(acc[c], 0.f);
    __syncthreads();   // all threads done reading g_pooled for this block's rows

    // zero this block's pooled slice + grid-strided cursor zero (for next replay)
    {
        float4 z4 = make_float4(0.f, 0.f, 0.f, 0.f);
        float4* ps = (float4*)&g_pooled[rowBase * DD];
        for (int i = tid; i < 64 * DD / 4; i += 256) ps[i] = z4;
        int4* cz = (int4*)g_cursor;
        int4 zi = make_int4(0, 0, 0, 0);
        for (int i = blockIdx.x * 256 + tid; i < NN / 4; i += (NG / 64) * 256) cz[i] = zi;
    }

    for (int i = tid; i < DD * DD / 4; i += 256)
        ((float4*)ws)[i] = ((const float4*)w2)[i];
    __syncthreads();

#pragma unroll
    for (int c = 0; c < 16; c++) acc[c] = b2[c0 + c];
    for (int k = 0; k < DD; k++) {
        float zv = zs[r * 65 + k];
        const float4* w4 = (const float4*)&ws[k * DD + c0];
        float4 a = w4[0], b = w4[1], cc = w4[2], d = w4[3];
        acc[0]  = fmaf(zv, a.x, acc[0]);   acc[1]  = fmaf(zv, a.y, acc[1]);
        acc[2]  = fmaf(zv, a.z, acc[2]);   acc[3]  = fmaf(zv, a.w, acc[3]);
        acc[4]  = fmaf(zv, b.x, acc[4]);   acc[5]  = fmaf(zv, b.y, acc[5]);
        acc[6]  = fmaf(zv, b.z, acc[6]);   acc[7]  = fmaf(zv, b.w, acc[7]);
        acc[8]  = fmaf(zv, cc.x, acc[8]);  acc[9]  = fmaf(zv, cc.y, acc[9]);
        acc[10] = fmaf(zv, cc.z, acc[10]); acc[11] = fmaf(zv, cc.w, acc[11]);
        acc[12] = fmaf(zv, d.x, acc[12]);  acc[13] = fmaf(zv, d.y, acc[13]);
        acc[14] = fmaf(zv, d.z, acc[14]);  acc[15] = fmaf(zv, d.w, acc[15]);
    }
    __syncthreads();
#pragma unroll
    for (int c = 0; c < 16; c++) zs[r * 65 + c0 + c] = fmaxf(acc[c], 0.f);
    __syncthreads();

    if ((tid & 3) == 0) {
        float s = b3[0];
        for (int k = 0; k < DD; k++) s = fmaf(zs[r * 65 + k], w3s[k], s);
        out[gr] = s;
    }
}

// ---------------- launch ----------------
extern "C" void kernel_launch(void* const* d_in, const int* in_sizes, int n_in,
                              void* d_out, int out_size) {
    const float* x      = (const float*)d_in[0];
    const int*   ei     = (const int*)d_in[1];
    const int*   batch  = (const int*)d_in[2];
    const float* Ws     = (const float*)d_in[3];
    const float* bs     = (const float*)d_in[4];
    const float* gamma  = (const float*)d_in[5];
    const float* beta   = (const float*)d_in[6];
    const float* w1     = (const float*)d_in[7];
    const float* b1     = (const float*)d_in[8];
    const float* w2     = (const float*)d_in[9];
    const float* b2     = (const float*)d_in[10];
    const float* w3     = (const float*)d_in[11];
    const float* b3     = (const float*)d_in[12];
    float* out = (float*)d_out;

    const int* src = ei;
    const int* dst = ei + NE;

    void *p_stats = nullptr, *p_acc = nullptr;
    cudaGetSymbolAddress(&p_stats, g_stats);
    cudaGetSymbolAddress(&p_acc, g_acc);
    float* stats = (float*)p_stats;

    cudaFuncSetAttribute(k_gemm, cudaFuncAttributeMaxDynamicSharedMemorySize, GEMM_SMEM);

    // CSR build (once per run; cursor zeroed by previous run's k_mlp / static init)
    k_hist<<<(NE + 255) / 256, 256>>>(dst);
    k_bsum<<<NB_SCAN, 256>>>();
    k_apply<<<NB_SCAN, 256>>>();
    k_fill<<<(NE + 255) / 256, 256>>>(src, dst);

    const float* hin = x;
    for (int l = 0; l < NL; l++) {
        k_gemm<<<(NN + GEMM_ROWS - 1) / GEMM_ROWS, 256, GEMM_SMEM>>>(
            hin, Ws + l * DD * DD,
            gamma + (l - 1) * DD, beta + (l - 1) * DD,
            stats + (l - 1) * 2 * DD,
            stats + l * 2 * DD, l > 0);
        k_aggr<<<2048, 256>>>(bs + l * DD, stats + l * 2 * DD);
        hin = (const float*)p_acc;
    }

    k_poolbn<<<(NN * 16 + 255) / 256, 256>>>(batch, gamma + 3 * DD, beta + 3 * DD,
                                             stats + 3 * 2 * DD);
    k_mlp<<<NG / 64, 256>>>(w1, b1, w2, b2, w3, b3, out);
}